// round 1
// baseline (speedup 1.0000x reference)
#include <cuda_runtime.h>

#define DI static __device__ __forceinline__

namespace {
constexpr int B = 2, S = 512, H = 128, A = 7;
constexpr int BS = B * S;
constexpr float LOG2E = 1.4426950408889634f;
constexpr float LN2   = 0.6931471805599453f;
constexpr float GK0   = -2.0f * LOG2E * 0.7978845608028654f;   // -2*log2(e)*sqrt(2/pi)
constexpr float GK1   = GK0 * 0.044715f;
constexpr float EPS   = 1e-5f;
}

// scratch: 0 = action pre (hiddens@aw1+ab1), 1 = hv_left, 2 = hd_left, 3 = hv_right, 4 = hd_right
__device__ float g_pre[5][BS * H];
__device__ float g_logits[BS * A];

DI float ex2a(float x){ float y; asm("ex2.approx.ftz.f32 %0, %1;" : "=f"(y) : "f"(x)); return y; }
DI float rcpa(float x){ float y; asm("rcp.approx.ftz.f32 %0, %1;" : "=f"(y) : "f"(x)); return y; }
DI float lg2a(float x){ float y; asm("lg2.approx.ftz.f32 %0, %1;" : "=f"(y) : "f"(x)); return y; }
DI float rsqa(float x){ float y; asm("rsqrt.approx.ftz.f32 %0, %1;" : "=f"(y) : "f"(x)); return y; }

// tanh-approx GeLU via sigmoid identity: x * sigmoid(2*a*(x + c x^3)) -> 1 EX2 + 1 RCP
DI float gelu_f(float x){
  float x2 = x * x;
  float w  = x * fmaf(GK1, x2, GK0);
  return x * rcpa(1.0f + ex2a(w));
}

DI float wredmax(float v){
  #pragma unroll
  for (int o = 16; o; o >>= 1) v = fmaxf(v, __shfl_xor_sync(0xffffffffu, v, o));
  return v;
}
DI float wredsum(float v){
  #pragma unroll
  for (int o = 16; o; o >>= 1) v += __shfl_xor_sync(0xffffffffu, v, o);
  return v;
}

// ---------------- P1: five [1024,128] @ [128,128] + bias GEMMs ----------------
// grid (64, 5), block 128. Each CTA: 16 rows x 128 cols, 4x4 register tile.
__global__ void __launch_bounds__(128) k_gemm(
    const float* __restrict__ x,
    const float* __restrict__ W0, const float* __restrict__ Bi0,
    const float* __restrict__ W1, const float* __restrict__ Bi1,
    const float* __restrict__ W2, const float* __restrict__ Bi2,
    const float* __restrict__ W3, const float* __restrict__ Bi3,
    const float* __restrict__ W4, const float* __restrict__ Bi4)
{
  __shared__ float xs[16][H];
  int m = blockIdx.y;
  const float* W = W0; const float* bias = Bi0;
  if      (m == 1){ W = W1; bias = Bi1; }
  else if (m == 2){ W = W2; bias = Bi2; }
  else if (m == 3){ W = W3; bias = Bi3; }
  else if (m == 4){ W = W4; bias = Bi4; }
  float* out = g_pre[m];

  int r0 = blockIdx.x * 16;
  int t  = threadIdx.x;
  #pragma unroll
  for (int r = 0; r < 16; ++r) xs[r][t] = x[(r0 + r) * H + t];
  __syncthreads();

  int rt = (t >> 5) * 4;       // 0,4,8,12
  int c0 = (t & 31) * 4;       // 0..124
  float4 bv = *(const float4*)&bias[c0];
  float acc[4][4];
  #pragma unroll
  for (int i = 0; i < 4; ++i){ acc[i][0]=bv.x; acc[i][1]=bv.y; acc[i][2]=bv.z; acc[i][3]=bv.w; }

  #pragma unroll 4
  for (int h = 0; h < H; ++h) {
    float4 w4 = *(const float4*)&W[h * H + c0];   // L1/L2-resident
    float xv[4];
    #pragma unroll
    for (int i = 0; i < 4; ++i) xv[i] = xs[rt + i][h];   // warp-uniform broadcast
    #pragma unroll
    for (int i = 0; i < 4; ++i){
      acc[i][0] = fmaf(xv[i], w4.x, acc[i][0]);
      acc[i][1] = fmaf(xv[i], w4.y, acc[i][1]);
      acc[i][2] = fmaf(xv[i], w4.z, acc[i][2]);
      acc[i][3] = fmaf(xv[i], w4.w, acc[i][3]);
    }
  }
  #pragma unroll
  for (int i = 0; i < 4; ++i){
    float4 o; o.x=acc[i][0]; o.y=acc[i][1]; o.z=acc[i][2]; o.w=acc[i][3];
    *(float4*)&out[(r0 + rt + i) * H + c0] = o;
  }
}

// ---------------- P2: action head rows: GeLU -> LN -> @aw2 + ab2 ----------------
// grid 1024 (one row), block 128.
__global__ void __launch_bounds__(128) k_action(
    const float* __restrict__ lng, const float* __restrict__ lnb,
    const float* __restrict__ aw2, const float* __restrict__ ab2)
{
  int row = blockIdx.x;
  int h   = threadIdx.x;
  float y = gelu_f(g_pre[0][row * H + h]);

  __shared__ float red1[4], red2[4], ys[H];
  float s1 = wredsum(y);
  float s2 = wredsum(y * y);
  int wid = h >> 5;
  if ((h & 31) == 0){ red1[wid] = s1; red2[wid] = s2; }
  __syncthreads();
  float t1 = red1[0] + red1[1] + red1[2] + red1[3];
  float t2 = red2[0] + red2[1] + red2[2] + red2[3];
  float mean = t1 * (1.0f / H);
  float var  = fmaf(-mean, mean, t2 * (1.0f / H));
  float rstd = rsqa(var + EPS);
  ys[h] = fmaf((y - mean) * rstd, lng[h], lnb[h]);
  __syncthreads();
  if (h < A){
    float acc = ab2[h];
    #pragma unroll 8
    for (int k = 0; k < H; ++k) acc = fmaf(ys[k], aw2[k * A + h], acc);
    g_logits[row * A + h] = acc;
  }
}

// ---------------- P3: action log_softmax over dim 1 (sequence) ----------------
// grid B*A = 14, block 512.
__global__ void __launch_bounds__(512) k_actsm(float* __restrict__ out)
{
  int b = blockIdx.x / A, a = blockIdx.x % A;
  int s = threadIdx.x;
  float v = g_logits[(b * S + s) * A + a];

  __shared__ float red[16];
  __shared__ float bmax_s, bsum_s;
  int wid = s >> 5, lane = s & 31;

  float m = wredmax(v);
  if (lane == 0) red[wid] = m;
  __syncthreads();
  if (s < 32){
    float tt = (s < 16) ? red[s] : -3.4e38f;
    tt = wredmax(tt);
    if (s == 0) bmax_s = tt;
  }
  __syncthreads();
  float bmax = bmax_s;
  float e = ex2a((v - bmax) * LOG2E);
  float sm = wredsum(e);
  __syncthreads();
  if (lane == 0) red[wid] = sm;
  __syncthreads();
  if (s < 32){
    float tt = (s < 16) ? red[s] : 0.0f;
    tt = wredsum(tt);
    if (s == 0) bsum_s = tt;
  }
  __syncthreads();
  out[(b * S + s) * A + a] = v - bmax - lg2a(bsum_s) * LN2;
}

// ---------------- P4: pointer heads, fused scores + log_softmax ----------------
// grid (S/4, B, 2 heads), block 256. CTA owns 4 i-rows; 8 j-tiles of 64.
// Per tile each thread owns one (i,j) pair; LN+projection collapsed to 3 sums.
__global__ void __launch_bounds__(256) k_ptr(
    const float* __restrict__ lg, const float* __restrict__ lb,
    const float* __restrict__ lpw, const float* __restrict__ lpb,
    const float* __restrict__ rg, const float* __restrict__ rb,
    const float* __restrict__ rpw, const float* __restrict__ rpb,
    float* __restrict__ out)
{
  int head = blockIdx.z, b = blockIdx.y;
  int i0 = blockIdx.x * 4;
  const float* gv = head ? rg  : lg;
  const float* bv = head ? rb  : lb;
  const float* pw = head ? rpw : lpw;
  const float* pb = head ? rpb : lpb;
  const float* hv = g_pre[1 + 2 * head] + b * S * H;   // indexed by j
  const float* hd = g_pre[2 + 2 * head] + b * S * H;   // indexed by i

  __shared__ __align__(16) float hvs[64][132];   // padded: conflict-free LDS.128
  __shared__ __align__(16) float hds[4][H];
  __shared__ __align__(16) float wgh[H];
  __shared__ float tmpb[H];
  __shared__ float cc2[2];
  __shared__ float redm[4][2], reds[4][2];

  int tid = threadIdx.x;
  if (tid < H){
    float p = pw[tid];
    wgh[tid]  = gv[tid] * p;
    tmpb[tid] = bv[tid] * p;
  }
  for (int idx = tid; idx < 4 * H; idx += 256)
    hds[idx >> 7][idx & (H - 1)] = hd[(i0 + (idx >> 7)) * H + (idx & (H - 1))];
  __syncthreads();
  if (tid == 0){
    float c1 = 0.f, c2 = 0.f;
    for (int h = 0; h < H; ++h){ c1 += wgh[h]; c2 += tmpb[h]; }
    cc2[0] = c1; cc2[1] = c2 + pb[0];
  }
  __syncthreads();
  float c1 = cc2[0], c2 = cc2[1];

  int it = tid >> 6;       // 0..3  (warp-pair uniform)
  int jt = tid & 63;       // 0..63
  float sc[8];

  for (int tile = 0; tile < 8; ++tile) {
    __syncthreads();
    for (int idx = tid; idx < 2048; idx += 256) {
      int r = idx >> 5, c = idx & 31;
      *(float4*)&hvs[r][c * 4] = *(const float4*)&hv[(tile * 64 + r) * H + c * 4];
    }
    __syncthreads();

    float s1 = 0.f, s2 = 0.f, s3 = 0.f;
    const float4* ar = (const float4*)&hvs[jt][0];
    const float4* dr = (const float4*)&hds[it][0];
    const float4* wr = (const float4*)&wgh[0];
    #pragma unroll 4
    for (int h4 = 0; h4 < 32; ++h4) {
      float4 a = ar[h4], d = dr[h4], w = wr[h4];
      float x, y;
      x = a.x + d.x; y = gelu_f(x); s1 += y; s2 = fmaf(y, y, s2); s3 = fmaf(y, w.x, s3);
      x = a.y + d.y; y = gelu_f(x); s1 += y; s2 = fmaf(y, y, s2); s3 = fmaf(y, w.y, s3);
      x = a.z + d.z; y = gelu_f(x); s1 += y; s2 = fmaf(y, y, s2); s3 = fmaf(y, w.z, s3);
      x = a.w + d.w; y = gelu_f(x); s1 += y; s2 = fmaf(y, y, s2); s3 = fmaf(y, w.w, s3);
    }
    float mean = s1 * (1.0f / H);
    float var  = fmaf(-mean, mean, s2 * (1.0f / H));
    float rstd = rsqa(var + EPS);
    sc[tile] = fmaf(rstd, fmaf(-mean, c1, s3), c2);
  }

  // fused log_softmax over j: row i held by 64 threads (2 warps) x 8 values
  float lmax = sc[0];
  #pragma unroll
  for (int k = 1; k < 8; ++k) lmax = fmaxf(lmax, sc[k]);
  lmax = wredmax(lmax);
  int wid = tid >> 5;
  if ((tid & 31) == 0) redm[it][wid & 1] = lmax;
  __syncthreads();
  float rmax = fmaxf(redm[it][0], redm[it][1]);
  float lsum = 0.f;
  #pragma unroll
  for (int k = 0; k < 8; ++k) lsum += ex2a((sc[k] - rmax) * LOG2E);
  lsum = wredsum(lsum);
  if ((tid & 31) == 0) reds[it][wid & 1] = lsum;
  __syncthreads();
  float lse = lg2a(reds[it][0] + reds[it][1]) * LN2;

  float* orow = out + B * S * A + head * (B * S * S) + (b * S + i0 + it) * S;
  #pragma unroll
  for (int k = 0; k < 8; ++k) orow[k * 64 + jt] = sc[k] - rmax - lse;
}

extern "C" void kernel_launch(void* const* d_in, const int* in_sizes, int n_in,
                              void* d_out, int out_size)
{
  (void)in_sizes; (void)n_in; (void)out_size;
  const float* hiddens = (const float*)d_in[0];
  const float* aw1     = (const float*)d_in[1];
  const float* ab1     = (const float*)d_in[2];
  const float* a_ln_g  = (const float*)d_in[3];
  const float* a_ln_b  = (const float*)d_in[4];
  const float* aw2     = (const float*)d_in[5];
  const float* ab2     = (const float*)d_in[6];
  const float* lhid_w  = (const float*)d_in[7];
  const float* lhid_b  = (const float*)d_in[8];
  const float* lhead_w = (const float*)d_in[9];
  const float* lhead_b = (const float*)d_in[10];
  const float* l_ln_g  = (const float*)d_in[11];
  const float* l_ln_b  = (const float*)d_in[12];
  const float* l_proj_w= (const float*)d_in[13];
  const float* l_proj_b= (const float*)d_in[14];
  const float* rhid_w  = (const float*)d_in[15];
  const float* rhid_b  = (const float*)d_in[16];
  const float* rhead_w = (const float*)d_in[17];
  const float* rhead_b = (const float*)d_in[18];
  const float* r_ln_g  = (const float*)d_in[19];
  const float* r_ln_b  = (const float*)d_in[20];
  const float* r_proj_w= (const float*)d_in[21];
  const float* r_proj_b= (const float*)d_in[22];
  float* out = (float*)d_out;

  k_gemm<<<dim3(BS / 16, 5), 128>>>(hiddens,
      aw1, ab1, lhid_w, lhid_b, lhead_w, lhead_b, rhid_w, rhid_b, rhead_w, rhead_b);
  k_action<<<BS, 128>>>(a_ln_g, a_ln_b, aw2, ab2);
  k_actsm<<<B * A, 512>>>(out);
  k_ptr<<<dim3(S / 4, B, 2), 256>>>(l_ln_g, l_ln_b, l_proj_w, l_proj_b,
                                    r_ln_g, r_ln_b, r_proj_w, r_proj_b, out);
}

// round 3
// speedup vs baseline: 1.1324x; 1.1324x over previous
#include <cuda_runtime.h>

#define DI static __device__ __forceinline__
typedef unsigned long long ull;

namespace {
constexpr int B = 2, S = 512, H = 128, A = 7;
constexpr int BS = B * S;
constexpr float LOG2E = 1.4426950408889634f;
constexpr float LN2   = 0.6931471805599453f;
constexpr float TK0   = 0.7978845608028654f;          // sqrt(2/pi)
constexpr float TK1   = TK0 * 0.044715f;
constexpr float GK0   = -2.0f * LOG2E * TK0;          // sigmoid-form consts (action head)
constexpr float GK1   = GK0 * 0.044715f;
constexpr float EPS   = 1e-5f;
}

// scratch: 0 = action pre (hiddens@aw1+ab1), 1 = hv_left, 2 = hd_left, 3 = hv_right, 4 = hd_right
__device__ float g_pre[5][BS * H];
__device__ float g_logits[BS * A];

DI float ex2a(float x){ float y; asm("ex2.approx.ftz.f32 %0, %1;" : "=f"(y) : "f"(x)); return y; }
DI float rcpa(float x){ float y; asm("rcp.approx.ftz.f32 %0, %1;" : "=f"(y) : "f"(x)); return y; }
DI float lg2a(float x){ float y; asm("lg2.approx.ftz.f32 %0, %1;" : "=f"(y) : "f"(x)); return y; }
DI float rsqa(float x){ float y; asm("rsqrt.approx.ftz.f32 %0, %1;" : "=f"(y) : "f"(x)); return y; }
DI float tanha(float x){ float y; asm("tanh.approx.f32 %0, %1;" : "=f"(y) : "f"(x)); return y; }

// ---- packed f32x2 helpers (sm_103a) ----
DI ull pk2(float x, float y){ ull r; asm("mov.b64 %0, {%1, %2};" : "=l"(r) : "f"(x), "f"(y)); return r; }
DI void upk2(ull v, float& x, float& y){ asm("mov.b64 {%0, %1}, %2;" : "=f"(x), "=f"(y) : "l"(v)); }
DI ull add2(ull a, ull b){ ull r; asm("add.rn.f32x2 %0, %1, %2;" : "=l"(r) : "l"(a), "l"(b)); return r; }
DI ull mul2(ull a, ull b){ ull r; asm("mul.rn.f32x2 %0, %1, %2;" : "=l"(r) : "l"(a), "l"(b)); return r; }
DI ull fma2(ull a, ull b, ull c){ ull r; asm("fma.rn.f32x2 %0, %1, %2, %3;" : "=l"(r) : "l"(a), "l"(b), "l"(c)); return r; }

// exact-ish gelu for the (tiny) action head
DI float gelu_f(float x){
  float x2 = x * x;
  float w  = x * fmaf(GK1, x2, GK0);
  return x * rcpa(1.0f + ex2a(w));
}

DI float wredmax(float v){
  #pragma unroll
  for (int o = 16; o; o >>= 1) v = fmaxf(v, __shfl_xor_sync(0xffffffffu, v, o));
  return v;
}
DI float wredsum(float v){
  #pragma unroll
  for (int o = 16; o; o >>= 1) v += __shfl_xor_sync(0xffffffffu, v, o);
  return v;
}

// ---------------- P1: five [1024,128] @ [128,128] + bias GEMMs ----------------
__global__ void __launch_bounds__(128) k_gemm(
    const float* __restrict__ x,
    const float* __restrict__ W0, const float* __restrict__ Bi0,
    const float* __restrict__ W1, const float* __restrict__ Bi1,
    const float* __restrict__ W2, const float* __restrict__ Bi2,
    const float* __restrict__ W3, const float* __restrict__ Bi3,
    const float* __restrict__ W4, const float* __restrict__ Bi4)
{
  __shared__ float xs[16][H];
  int m = blockIdx.y;
  const float* W = W0; const float* bias = Bi0;
  if      (m == 1){ W = W1; bias = Bi1; }
  else if (m == 2){ W = W2; bias = Bi2; }
  else if (m == 3){ W = W3; bias = Bi3; }
  else if (m == 4){ W = W4; bias = Bi4; }
  float* out = g_pre[m];

  int r0 = blockIdx.x * 16;
  int t  = threadIdx.x;
  #pragma unroll
  for (int r = 0; r < 16; ++r) xs[r][t] = x[(r0 + r) * H + t];
  __syncthreads();

  int rt = (t >> 5) * 4;
  int c0 = (t & 31) * 4;
  float4 bv = *(const float4*)&bias[c0];
  float acc[4][4];
  #pragma unroll
  for (int i = 0; i < 4; ++i){ acc[i][0]=bv.x; acc[i][1]=bv.y; acc[i][2]=bv.z; acc[i][3]=bv.w; }

  #pragma unroll 4
  for (int h = 0; h < H; ++h) {
    float4 w4 = *(const float4*)&W[h * H + c0];
    float xv[4];
    #pragma unroll
    for (int i = 0; i < 4; ++i) xv[i] = xs[rt + i][h];
    #pragma unroll
    for (int i = 0; i < 4; ++i){
      acc[i][0] = fmaf(xv[i], w4.x, acc[i][0]);
      acc[i][1] = fmaf(xv[i], w4.y, acc[i][1]);
      acc[i][2] = fmaf(xv[i], w4.z, acc[i][2]);
      acc[i][3] = fmaf(xv[i], w4.w, acc[i][3]);
    }
  }
  #pragma unroll
  for (int i = 0; i < 4; ++i){
    float4 o; o.x=acc[i][0]; o.y=acc[i][1]; o.z=acc[i][2]; o.w=acc[i][3];
    *(float4*)&out[(r0 + rt + i) * H + c0] = o;
  }
}

// ---------------- P2: action head rows: GeLU -> LN -> @aw2 + ab2 ----------------
__global__ void __launch_bounds__(128) k_action(
    const float* __restrict__ lng, const float* __restrict__ lnb,
    const float* __restrict__ aw2, const float* __restrict__ ab2)
{
  int row = blockIdx.x;
  int h   = threadIdx.x;
  float y = gelu_f(g_pre[0][row * H + h]);

  __shared__ float red1[4], red2[4], ys[H];
  float s1 = wredsum(y);
  float s2 = wredsum(y * y);
  int wid = h >> 5;
  if ((h & 31) == 0){ red1[wid] = s1; red2[wid] = s2; }
  __syncthreads();
  float t1 = red1[0] + red1[1] + red1[2] + red1[3];
  float t2 = red2[0] + red2[1] + red2[2] + red2[3];
  float mean = t1 * (1.0f / H);
  float var  = fmaf(-mean, mean, t2 * (1.0f / H));
  float rstd = rsqa(var + EPS);
  ys[h] = fmaf((y - mean) * rstd, lng[h], lnb[h]);
  __syncthreads();
  if (h < A){
    float acc = ab2[h];
    #pragma unroll 8
    for (int k = 0; k < H; ++k) acc = fmaf(ys[k], aw2[k * A + h], acc);
    g_logits[row * A + h] = acc;
  }
}

// ---------------- P3: action log_softmax over dim 1 (sequence) ----------------
__global__ void __launch_bounds__(512) k_actsm(float* __restrict__ out)
{
  int b = blockIdx.x / A, a = blockIdx.x % A;
  int s = threadIdx.x;
  float v = g_logits[(b * S + s) * A + a];

  __shared__ float red[16];
  __shared__ float bmax_s, bsum_s;
  int wid = s >> 5, lane = s & 31;

  float m = wredmax(v);
  if (lane == 0) red[wid] = m;
  __syncthreads();
  if (s < 32){
    float tt = (s < 16) ? red[s] : -3.4e38f;
    tt = wredmax(tt);
    if (s == 0) bmax_s = tt;
  }
  __syncthreads();
  float bmax = bmax_s;
  float e = ex2a((v - bmax) * LOG2E);
  float sm = wredsum(e);
  __syncthreads();
  if (lane == 0) red[wid] = sm;
  __syncthreads();
  if (s < 32){
    float tt = (s < 16) ? red[s] : 0.0f;
    tt = wredsum(tt);
    if (s == 0) bsum_s = tt;
  }
  __syncthreads();
  out[(b * S + s) * A + a] = v - bmax - lg2a(bsum_s) * LN2;
}

// ---------------- P4: pointer heads (packed f32x2 + HW tanh) ----------------
// grid (S/4, B, 2), block 128. Warp = one i-row; lane = j within 32-wide tile.
// 16 j-tiles; LN+proj collapsed to 3 packed running sums; warp-local log-softmax.
__global__ void __launch_bounds__(128) k_ptr(
    const float* __restrict__ lg, const float* __restrict__ lb,
    const float* __restrict__ lpw, const float* __restrict__ lpb,
    const float* __restrict__ rg, const float* __restrict__ rb,
    const float* __restrict__ rpw, const float* __restrict__ rpb,
    float* __restrict__ out)
{
  int head = blockIdx.z, b = blockIdx.y;
  int i0 = blockIdx.x * 4;
  const float* gv = head ? rg  : lg;
  const float* bv = head ? rb  : lb;
  const float* pw = head ? rpw : lpw;
  const float* pb = head ? rpb : lpb;
  const float* hv = g_pre[1 + 2 * head] + b * S * H;   // indexed by j
  const float* hd = g_pre[2 + 2 * head] + b * S * H;   // indexed by i

  __shared__ __align__(16) float hvs[32][132];   // padded rows
  __shared__ __align__(16) float hds[4][H];
  __shared__ __align__(16) float wgh[H];
  __shared__ float redc[4][2];
  __shared__ float cc2[2];

  int tid = threadIdx.x;
  int wid = tid >> 5, lane = tid & 31;

  // per-channel folded weights: wgh = g*pw ; c1 = sum(g*pw) ; c2 = sum(b*pw) + pb
  {
    float p  = pw[tid];
    float wg = gv[tid] * p;
    float tb = bv[tid] * p;
    wgh[tid] = wg;
    float r1 = wredsum(wg), r2 = wredsum(tb);
    if (lane == 0){ redc[wid][0] = r1; redc[wid][1] = r2; }
  }
  for (int idx = tid; idx < 4 * H; idx += 128)
    hds[idx >> 7][idx & (H - 1)] = hd[(i0 + (idx >> 7)) * H + (idx & (H - 1))];
  __syncthreads();
  if (tid == 0){
    cc2[0] = redc[0][0] + redc[1][0] + redc[2][0] + redc[3][0];
    cc2[1] = redc[0][1] + redc[1][1] + redc[2][1] + redc[3][1] + pb[0];
  }
  __syncthreads();
  float c1 = cc2[0], c2 = cc2[1];

  const ull K0p = pk2(TK0, TK0);
  const ull K1p = pk2(TK1, TK1);
  const ull HLp = pk2(0.5f, 0.5f);

  float sc[16];

  for (int tile = 0; tile < 16; ++tile) {
    __syncthreads();
    #pragma unroll
    for (int k = 0; k < 8; ++k) {
      int idx = tid + k * 128;
      int r = idx >> 5, c = idx & 31;
      *(float4*)&hvs[r][c * 4] = *(const float4*)&hv[(tile * 32 + r) * H + c * 4];
    }
    __syncthreads();

    ull s1 = 0, s2 = 0, s3 = 0;   // packed accumulators (0.0f,0.0f)
    const ull* ar = (const ull*)&hvs[lane][0];
    const ull* dr = (const ull*)&hds[wid][0];
    const ull* wr = (const ull*)&wgh[0];
    #pragma unroll 8
    for (int q = 0; q < 64; ++q) {   // H=128 floats = 64 f32x2 packs
      ull a = ar[q];
      ull d = dr[q];
      ull w = wr[q];
      ull x  = add2(a, d);
      ull x2 = mul2(x, x);
      ull p  = fma2(K1p, x2, K0p);
      ull u  = mul2(x, p);
      float u0, u1; upk2(u, u0, u1);
      ull t  = pk2(tanha(u0), tanha(u1));
      ull xh = mul2(x, HLp);
      ull y  = fma2(xh, t, xh);
      s1 = add2(s1, y);
      s2 = fma2(y, y, s2);
      s3 = fma2(y, w, s3);
    }
    float a0,a1,b0,b1,d0,d1;
    upk2(s1, a0, a1); upk2(s2, b0, b1); upk2(s3, d0, d1);
    float t1 = a0 + a1, t2 = b0 + b1, t3 = d0 + d1;
    float mean = t1 * (1.0f / H);
    float var  = fmaf(-mean, mean, t2 * (1.0f / H));
    float rstd = rsqa(var + EPS);
    sc[tile] = fmaf(rstd, fmaf(-mean, c1, t3), c2);
  }

  // warp-local log_softmax over j (this warp owns row i = i0 + wid entirely)
  float lmax = sc[0];
  #pragma unroll
  for (int k = 1; k < 16; ++k) lmax = fmaxf(lmax, sc[k]);
  lmax = wredmax(lmax);
  float lsum = 0.f;
  #pragma unroll
  for (int k = 0; k < 16; ++k) lsum += ex2a((sc[k] - lmax) * LOG2E);
  lsum = wredsum(lsum);
  float lse = lg2a(lsum) * LN2;

  float* orow = out + B * S * A + head * (B * S * S) + (b * S + i0 + wid) * S;
  #pragma unroll
  for (int k = 0; k < 16; ++k) orow[k * 32 + lane] = sc[k] - lmax - lse;
}

extern "C" void kernel_launch(void* const* d_in, const int* in_sizes, int n_in,
                              void* d_out, int out_size)
{
  (void)in_sizes; (void)n_in; (void)out_size;
  const float* hiddens = (const float*)d_in[0];
  const float* aw1     = (const float*)d_in[1];
  const float* ab1     = (const float*)d_in[2];
  const float* a_ln_g  = (const float*)d_in[3];
  const float* a_ln_b  = (const float*)d_in[4];
  const float* aw2     = (const float*)d_in[5];
  const float* ab2     = (const float*)d_in[6];
  const float* lhid_w  = (const float*)d_in[7];
  const float* lhid_b  = (const float*)d_in[8];
  const float* lhead_w = (const float*)d_in[9];
  const float* lhead_b = (const float*)d_in[10];
  const float* l_ln_g  = (const float*)d_in[11];
  const float* l_ln_b  = (const float*)d_in[12];
  const float* l_proj_w= (const float*)d_in[13];
  const float* l_proj_b= (const float*)d_in[14];
  const float* rhid_w  = (const float*)d_in[15];
  const float* rhid_b  = (const float*)d_in[16];
  const float* rhead_w = (const float*)d_in[17];
  const float* rhead_b = (const float*)d_in[18];
  const float* r_ln_g  = (const float*)d_in[19];
  const float* r_ln_b  = (const float*)d_in[20];
  const float* r_proj_w= (const float*)d_in[21];
  const float* r_proj_b= (const float*)d_in[22];
  float* out = (float*)d_out;

  k_gemm<<<dim3(BS / 16, 5), 128>>>(hiddens,
      aw1, ab1, lhid_w, lhid_b, lhead_w, lhead_b, rhid_w, rhid_b, rhead_w, rhead_b);
  k_action<<<BS, 128>>>(a_ln_g, a_ln_b, aw2, ab2);
  k_actsm<<<B * A, 512>>>(out);
  k_ptr<<<dim3(S / 4, B, 2), 128>>>(l_ln_g, l_ln_b, l_proj_w, l_proj_b,
                                    r_ln_g, r_ln_b, r_proj_w, r_proj_b, out);
}

// round 4
// speedup vs baseline: 1.1405x; 1.0071x over previous
#include <cuda_runtime.h>

#define DI static __device__ __forceinline__
typedef unsigned long long ull;

namespace {
constexpr int B = 2, S = 512, H = 128, A = 7;
constexpr int BS = B * S;
constexpr float LOG2E = 1.4426950408889634f;
constexpr float LN2   = 0.6931471805599453f;
constexpr float TK0   = 0.7978845608028654f;          // sqrt(2/pi)
constexpr float TK1   = TK0 * 0.044715f;
constexpr float GK0   = -2.0f * LOG2E * TK0;          // sigmoid-form consts (action head)
constexpr float GK1   = GK0 * 0.044715f;
constexpr float EPS   = 1e-5f;
}

// scratch: 0 = action pre (hiddens@aw1+ab1), 1 = hv_left, 2 = hd_left, 3 = hv_right, 4 = hd_right
__device__ __align__(16) float g_pre[5][BS * H];
__device__ float g_logits[BS * A];

DI float ex2a(float x){ float y; asm("ex2.approx.ftz.f32 %0, %1;" : "=f"(y) : "f"(x)); return y; }
DI float rcpa(float x){ float y; asm("rcp.approx.ftz.f32 %0, %1;" : "=f"(y) : "f"(x)); return y; }
DI float lg2a(float x){ float y; asm("lg2.approx.ftz.f32 %0, %1;" : "=f"(y) : "f"(x)); return y; }
DI float rsqa(float x){ float y; asm("rsqrt.approx.ftz.f32 %0, %1;" : "=f"(y) : "f"(x)); return y; }
DI float tanha(float x){ float y; asm("tanh.approx.f32 %0, %1;" : "=f"(y) : "f"(x)); return y; }

// ---- packed f32x2 helpers (sm_103a) ----
DI ull pk2(float x, float y){ ull r; asm("mov.b64 %0, {%1, %2};" : "=l"(r) : "f"(x), "f"(y)); return r; }
DI void upk2(ull v, float& x, float& y){ asm("mov.b64 {%0, %1}, %2;" : "=f"(x), "=f"(y) : "l"(v)); }
DI ull add2(ull a, ull b){ ull r; asm("add.rn.f32x2 %0, %1, %2;" : "=l"(r) : "l"(a), "l"(b)); return r; }
DI ull mul2(ull a, ull b){ ull r; asm("mul.rn.f32x2 %0, %1, %2;" : "=l"(r) : "l"(a), "l"(b)); return r; }
DI ull fma2(ull a, ull b, ull c){ ull r; asm("fma.rn.f32x2 %0, %1, %2, %3;" : "=l"(r) : "l"(a), "l"(b), "l"(c)); return r; }

// exact-ish gelu for the (tiny) action head
DI float gelu_f(float x){
  float x2 = x * x;
  float w  = x * fmaf(GK1, x2, GK0);
  return x * rcpa(1.0f + ex2a(w));
}

DI float wredmax(float v){
  #pragma unroll
  for (int o = 16; o; o >>= 1) v = fmaxf(v, __shfl_xor_sync(0xffffffffu, v, o));
  return v;
}
DI float wredsum(float v){
  #pragma unroll
  for (int o = 16; o; o >>= 1) v += __shfl_xor_sync(0xffffffffu, v, o);
  return v;
}

// ---------------- P1: five [1024,128] @ [128,128] + bias GEMMs ----------------
__global__ void __launch_bounds__(128) k_gemm(
    const float* __restrict__ x,
    const float* __restrict__ W0, const float* __restrict__ Bi0,
    const float* __restrict__ W1, const float* __restrict__ Bi1,
    const float* __restrict__ W2, const float* __restrict__ Bi2,
    const float* __restrict__ W3, const float* __restrict__ Bi3,
    const float* __restrict__ W4, const float* __restrict__ Bi4)
{
  __shared__ float xs[16][H];
  int m = blockIdx.y;
  const float* W = W0; const float* bias = Bi0;
  if      (m == 1){ W = W1; bias = Bi1; }
  else if (m == 2){ W = W2; bias = Bi2; }
  else if (m == 3){ W = W3; bias = Bi3; }
  else if (m == 4){ W = W4; bias = Bi4; }
  float* out = g_pre[m];

  int r0 = blockIdx.x * 16;
  int t  = threadIdx.x;
  #pragma unroll
  for (int r = 0; r < 16; ++r) xs[r][t] = x[(r0 + r) * H + t];
  __syncthreads();

  int rt = (t >> 5) * 4;
  int c0 = (t & 31) * 4;
  float4 bv = *(const float4*)&bias[c0];
  float acc[4][4];
  #pragma unroll
  for (int i = 0; i < 4; ++i){ acc[i][0]=bv.x; acc[i][1]=bv.y; acc[i][2]=bv.z; acc[i][3]=bv.w; }

  #pragma unroll 4
  for (int h = 0; h < H; ++h) {
    float4 w4 = *(const float4*)&W[h * H + c0];
    float xv[4];
    #pragma unroll
    for (int i = 0; i < 4; ++i) xv[i] = xs[rt + i][h];
    #pragma unroll
    for (int i = 0; i < 4; ++i){
      acc[i][0] = fmaf(xv[i], w4.x, acc[i][0]);
      acc[i][1] = fmaf(xv[i], w4.y, acc[i][1]);
      acc[i][2] = fmaf(xv[i], w4.z, acc[i][2]);
      acc[i][3] = fmaf(xv[i], w4.w, acc[i][3]);
    }
  }
  #pragma unroll
  for (int i = 0; i < 4; ++i){
    float4 o; o.x=acc[i][0]; o.y=acc[i][1]; o.z=acc[i][2]; o.w=acc[i][3];
    *(float4*)&out[(r0 + rt + i) * H + c0] = o;
  }
}

// ---------------- P2: action head rows: GeLU -> LN -> @aw2 + ab2 ----------------
__global__ void __launch_bounds__(128) k_action(
    const float* __restrict__ lng, const float* __restrict__ lnb,
    const float* __restrict__ aw2, const float* __restrict__ ab2)
{
  int row = blockIdx.x;
  int h   = threadIdx.x;
  float y = gelu_f(g_pre[0][row * H + h]);

  __shared__ float red1[4], red2[4], ys[H];
  float s1 = wredsum(y);
  float s2 = wredsum(y * y);
  int wid = h >> 5;
  if ((h & 31) == 0){ red1[wid] = s1; red2[wid] = s2; }
  __syncthreads();
  float t1 = red1[0] + red1[1] + red1[2] + red1[3];
  float t2 = red2[0] + red2[1] + red2[2] + red2[3];
  float mean = t1 * (1.0f / H);
  float var  = fmaf(-mean, mean, t2 * (1.0f / H));
  float rstd = rsqa(var + EPS);
  ys[h] = fmaf((y - mean) * rstd, lng[h], lnb[h]);
  __syncthreads();
  if (h < A){
    float acc = ab2[h];
    #pragma unroll 8
    for (int k = 0; k < H; ++k) acc = fmaf(ys[k], aw2[k * A + h], acc);
    g_logits[row * A + h] = acc;
  }
}

// ---------------- P3: action log_softmax over dim 1 (sequence) ----------------
__global__ void __launch_bounds__(512) k_actsm(float* __restrict__ out)
{
  int b = blockIdx.x / A, a = blockIdx.x % A;
  int s = threadIdx.x;
  float v = g_logits[(b * S + s) * A + a];

  __shared__ float red[16];
  __shared__ float bmax_s, bsum_s;
  int wid = s >> 5, lane = s & 31;

  float m = wredmax(v);
  if (lane == 0) red[wid] = m;
  __syncthreads();
  if (s < 32){
    float tt = (s < 16) ? red[s] : -3.4e38f;
    tt = wredmax(tt);
    if (s == 0) bmax_s = tt;
  }
  __syncthreads();
  float bmax = bmax_s;
  float e = ex2a((v - bmax) * LOG2E);
  float sm = wredsum(e);
  __syncthreads();
  if (lane == 0) red[wid] = sm;
  __syncthreads();
  if (s < 32){
    float tt = (s < 16) ? red[s] : 0.0f;
    tt = wredsum(tt);
    if (s == 0) bsum_s = tt;
  }
  __syncthreads();
  out[(b * S + s) * A + a] = v - bmax - lg2a(bsum_s) * LN2;
}

// ---------------- P4: pointer heads (f32x2 + HW tanh, j-split warp groups) ----
// grid (S/4, B, 2), block 256 = 8 warps: group g = wid>>2 handles j-half g,
// warp's i-row = wid&3. Swizzled smem (u ^ (r&15)) -> conflict-free LDS.64/STS.64.
__global__ void __launch_bounds__(256) k_ptr(
    const float* __restrict__ lg, const float* __restrict__ lb,
    const float* __restrict__ lpw, const float* __restrict__ lpb,
    const float* __restrict__ rg, const float* __restrict__ rb,
    const float* __restrict__ rpw, const float* __restrict__ rpb,
    float* __restrict__ out)
{
  int head = blockIdx.z, b = blockIdx.y;
  int i0 = blockIdx.x * 4;
  const float* gv = head ? rg  : lg;
  const float* bv = head ? rb  : lb;
  const float* pw = head ? rpw : lpw;
  const float* pb = head ? rpb : lpb;
  const float* hv = g_pre[1 + 2 * head] + b * S * H;   // indexed by j
  const float* hd = g_pre[2 + 2 * head] + b * S * H;   // indexed by i

  __shared__ __align__(16) ull  hvs[2][32][64];   // XOR-swizzled, 32KB
  __shared__ __align__(16) float hds[4][H];
  __shared__ __align__(16) float wgh[H];
  __shared__ float redc[4][2];
  __shared__ float cc2[2];
  __shared__ float gmaxs[2][4], gsums[2][4];

  int tid  = threadIdx.x;
  int wid  = tid >> 5, lane = tid & 31;
  int g    = tid >> 7;        // j-half group (0/1)
  int gt   = tid & 127;       // index within group
  int ir   = wid & 3;         // i-row within CTA

  // folded weights: wgh = g*pw ; c1 = sum(g*pw) ; c2 = sum(b*pw) + pb
  if (tid < 128) {
    float p  = pw[tid];
    float wg = gv[tid] * p;
    float tb = bv[tid] * p;
    wgh[tid] = wg;
    float r1 = wredsum(wg), r2 = wredsum(tb);
    if (lane == 0){ redc[wid][0] = r1; redc[wid][1] = r2; }
  }
  for (int idx = tid; idx < 4 * H; idx += 256)
    hds[idx >> 7][idx & (H - 1)] = hd[(i0 + (idx >> 7)) * H + (idx & (H - 1))];
  __syncthreads();
  if (tid == 0){
    cc2[0] = redc[0][0] + redc[1][0] + redc[2][0] + redc[3][0];
    cc2[1] = redc[0][1] + redc[1][1] + redc[2][1] + redc[3][1] + pb[0];
  }
  __syncthreads();
  float c1 = cc2[0], c2 = cc2[1];

  const ull K0p = pk2(TK0, TK0);
  const ull K1p = pk2(TK1, TK1);
  const ull HLp = pk2(0.5f, 0.5f);
  const ull* hv8 = (const ull*)hv;   // 64 ulls per row

  float sc[8];
  int barid = 1 + g;
  int sw = lane & 15;

  for (int tile = 0; tile < 8; ++tile) {
    int tt = g * 8 + tile;
    asm volatile("bar.sync %0, 128;" :: "r"(barid) : "memory");
    // stage 32 rows x 64 ull, swizzled; warp covers 32 consecutive u of one row
    #pragma unroll
    for (int k = 0; k < 16; ++k) {
      int idx = gt + k * 128;
      int r = idx >> 6, u = idx & 63;
      hvs[g][r][u ^ (r & 15)] = hv8[(tt * 32 + r) * 64 + u];
    }
    asm volatile("bar.sync %0, 128;" :: "r"(barid) : "memory");

    ull s1 = 0, s2 = 0, s3 = 0;
    const ull* ar = &hvs[g][lane][0];
    const ull* dr = (const ull*)&hds[ir][0];
    const ull* wr = (const ull*)&wgh[0];
    #pragma unroll 8
    for (int q = 0; q < 64; ++q) {
      ull a = ar[q ^ sw];
      ull d = dr[q];
      ull w = wr[q];
      ull x  = add2(a, d);
      ull x2 = mul2(x, x);
      ull p  = fma2(K1p, x2, K0p);
      ull u  = mul2(x, p);
      float u0, u1; upk2(u, u0, u1);
      ull t  = pk2(tanha(u0), tanha(u1));
      ull xh = mul2(x, HLp);
      ull y  = fma2(xh, t, xh);
      s1 = add2(s1, y);
      s2 = fma2(y, y, s2);
      s3 = fma2(y, w, s3);
    }
    float a0,a1,b0,b1,d0,d1;
    upk2(s1, a0, a1); upk2(s2, b0, b1); upk2(s3, d0, d1);
    float t1 = a0 + a1, t2 = b0 + b1, t3 = d0 + d1;
    float mean = t1 * (1.0f / H);
    float var  = fmaf(-mean, mean, t2 * (1.0f / H));
    float rstd = rsqa(var + EPS);
    sc[tile] = fmaf(rstd, fmaf(-mean, c1, t3), c2);
  }

  // log_softmax over j: combine the two j-half groups per i-row
  float lmax = sc[0];
  #pragma unroll
  for (int k = 1; k < 8; ++k) lmax = fmaxf(lmax, sc[k]);
  lmax = wredmax(lmax);
  if (lane == 0) gmaxs[g][ir] = lmax;
  __syncthreads();
  float m = fmaxf(gmaxs[0][ir], gmaxs[1][ir]);
  float lsum = 0.f;
  #pragma unroll
  for (int k = 0; k < 8; ++k) lsum += ex2a((sc[k] - m) * LOG2E);
  lsum = wredsum(lsum);
  if (lane == 0) gsums[g][ir] = lsum;
  __syncthreads();
  float lse = lg2a(gsums[0][ir] + gsums[1][ir]) * LN2;

  float* orow = out + B * S * A + head * (B * S * S) + (b * S + i0 + ir) * S + g * 256;
  #pragma unroll
  for (int k = 0; k < 8; ++k) orow[k * 32 + lane] = sc[k] - m - lse;
}

extern "C" void kernel_launch(void* const* d_in, const int* in_sizes, int n_in,
                              void* d_out, int out_size)
{
  (void)in_sizes; (void)n_in; (void)out_size;
  const float* hiddens = (const float*)d_in[0];
  const float* aw1     = (const float*)d_in[1];
  const float* ab1     = (const float*)d_in[2];
  const float* a_ln_g  = (const float*)d_in[3];
  const float* a_ln_b  = (const float*)d_in[4];
  const float* aw2     = (const float*)d_in[5];
  const float* ab2     = (const float*)d_in[6];
  const float* lhid_w  = (const float*)d_in[7];
  const float* lhid_b  = (const float*)d_in[8];
  const float* lhead_w = (const float*)d_in[9];
  const float* lhead_b = (const float*)d_in[10];
  const float* l_ln_g  = (const float*)d_in[11];
  const float* l_ln_b  = (const float*)d_in[12];
  const float* l_proj_w= (const float*)d_in[13];
  const float* l_proj_b= (const float*)d_in[14];
  const float* rhid_w  = (const float*)d_in[15];
  const float* rhid_b  = (const float*)d_in[16];
  const float* rhead_w = (const float*)d_in[17];
  const float* rhead_b = (const float*)d_in[18];
  const float* r_ln_g  = (const float*)d_in[19];
  const float* r_ln_b  = (const float*)d_in[20];
  const float* r_proj_w= (const float*)d_in[21];
  const float* r_proj_b= (const float*)d_in[22];
  float* out = (float*)d_out;

  k_gemm<<<dim3(BS / 16, 5), 128>>>(hiddens,
      aw1, ab1, lhid_w, lhid_b, lhead_w, lhead_b, rhid_w, rhid_b, rhead_w, rhead_b);
  k_action<<<BS, 128>>>(a_ln_g, a_ln_b, aw2, ab2);
  k_actsm<<<B * A, 512>>>(out);
  k_ptr<<<dim3(S / 4, B, 2), 256>>>(l_ln_g, l_ln_b, l_proj_w, l_proj_b,
                                    r_ln_g, r_ln_b, r_proj_w, r_proj_b, out);
}

// round 5
// speedup vs baseline: 1.2718x; 1.1151x over previous
#include <cuda_runtime.h>

#define DI static __device__ __forceinline__
typedef unsigned long long ull;

namespace {
constexpr int B = 2, S = 512, H = 128, A = 7;
constexpr int BS = B * S;
constexpr float LOG2E = 1.4426950408889634f;
constexpr float LN2   = 0.6931471805599453f;
constexpr float TK0   = 0.7978845608028654f;          // sqrt(2/pi)
constexpr float TK1   = TK0 * 0.044715f;
constexpr float GK0   = -2.0f * LOG2E * TK0;          // sigmoid-form consts (action head)
constexpr float GK1   = GK0 * 0.044715f;
constexpr float EPS   = 1e-5f;
}

// scratch: 0 = action pre (hiddens@aw1+ab1), 1 = hv_left, 2 = hd_left, 3 = hv_right, 4 = hd_right
__device__ __align__(16) float g_pre[5][BS * H];
__device__ float g_logits[BS * A];

DI float ex2a(float x){ float y; asm("ex2.approx.ftz.f32 %0, %1;" : "=f"(y) : "f"(x)); return y; }
DI float rcpa(float x){ float y; asm("rcp.approx.ftz.f32 %0, %1;" : "=f"(y) : "f"(x)); return y; }
DI float lg2a(float x){ float y; asm("lg2.approx.ftz.f32 %0, %1;" : "=f"(y) : "f"(x)); return y; }
DI float rsqa(float x){ float y; asm("rsqrt.approx.ftz.f32 %0, %1;" : "=f"(y) : "f"(x)); return y; }
DI float tanha(float x){ float y; asm("tanh.approx.f32 %0, %1;" : "=f"(y) : "f"(x)); return y; }

// ---- packed f32x2 helpers (sm_103a) ----
DI ull pk2(float x, float y){ ull r; asm("mov.b64 %0, {%1, %2};" : "=l"(r) : "f"(x), "f"(y)); return r; }
DI void upk2(ull v, float& x, float& y){ asm("mov.b64 {%0, %1}, %2;" : "=f"(x), "=f"(y) : "l"(v)); }
DI ull add2(ull a, ull b){ ull r; asm("add.rn.f32x2 %0, %1, %2;" : "=l"(r) : "l"(a), "l"(b)); return r; }
DI ull mul2(ull a, ull b){ ull r; asm("mul.rn.f32x2 %0, %1, %2;" : "=l"(r) : "l"(a), "l"(b)); return r; }
DI ull fma2(ull a, ull b, ull c){ ull r; asm("fma.rn.f32x2 %0, %1, %2, %3;" : "=l"(r) : "l"(a), "l"(b), "l"(c)); return r; }

// exact-ish gelu for the (tiny) action head
DI float gelu_f(float x){
  float x2 = x * x;
  float w  = x * fmaf(GK1, x2, GK0);
  return x * rcpa(1.0f + ex2a(w));
}

DI float wredmax(float v){
  #pragma unroll
  for (int o = 16; o; o >>= 1) v = fmaxf(v, __shfl_xor_sync(0xffffffffu, v, o));
  return v;
}
DI float wredsum(float v){
  #pragma unroll
  for (int o = 16; o; o >>= 1) v += __shfl_xor_sync(0xffffffffu, v, o);
  return v;
}

// ---------------- P1: five [1024,128] @ [128,128] + bias GEMMs ----------------
__global__ void __launch_bounds__(128) k_gemm(
    const float* __restrict__ x,
    const float* __restrict__ W0, const float* __restrict__ Bi0,
    const float* __restrict__ W1, const float* __restrict__ Bi1,
    const float* __restrict__ W2, const float* __restrict__ Bi2,
    const float* __restrict__ W3, const float* __restrict__ Bi3,
    const float* __restrict__ W4, const float* __restrict__ Bi4)
{
  __shared__ float xs[16][H];
  int m = blockIdx.y;
  const float* W = W0; const float* bias = Bi0;
  if      (m == 1){ W = W1; bias = Bi1; }
  else if (m == 2){ W = W2; bias = Bi2; }
  else if (m == 3){ W = W3; bias = Bi3; }
  else if (m == 4){ W = W4; bias = Bi4; }
  float* out = g_pre[m];

  int r0 = blockIdx.x * 16;
  int t  = threadIdx.x;
  #pragma unroll
  for (int r = 0; r < 16; ++r) xs[r][t] = x[(r0 + r) * H + t];
  __syncthreads();

  int rt = (t >> 5) * 4;
  int c0 = (t & 31) * 4;
  float4 bv = *(const float4*)&bias[c0];
  float acc[4][4];
  #pragma unroll
  for (int i = 0; i < 4; ++i){ acc[i][0]=bv.x; acc[i][1]=bv.y; acc[i][2]=bv.z; acc[i][3]=bv.w; }

  #pragma unroll 4
  for (int h = 0; h < H; ++h) {
    float4 w4 = *(const float4*)&W[h * H + c0];
    float xv[4];
    #pragma unroll
    for (int i = 0; i < 4; ++i) xv[i] = xs[rt + i][h];
    #pragma unroll
    for (int i = 0; i < 4; ++i){
      acc[i][0] = fmaf(xv[i], w4.x, acc[i][0]);
      acc[i][1] = fmaf(xv[i], w4.y, acc[i][1]);
      acc[i][2] = fmaf(xv[i], w4.z, acc[i][2]);
      acc[i][3] = fmaf(xv[i], w4.w, acc[i][3]);
    }
  }
  #pragma unroll
  for (int i = 0; i < 4; ++i){
    float4 o; o.x=acc[i][0]; o.y=acc[i][1]; o.z=acc[i][2]; o.w=acc[i][3];
    *(float4*)&out[(r0 + rt + i) * H + c0] = o;
  }
}

// ---------------- P2: action head rows: GeLU -> LN -> @aw2 + ab2 ----------------
__global__ void __launch_bounds__(128) k_action(
    const float* __restrict__ lng, const float* __restrict__ lnb,
    const float* __restrict__ aw2, const float* __restrict__ ab2)
{
  int row = blockIdx.x;
  int h   = threadIdx.x;
  float y = gelu_f(g_pre[0][row * H + h]);

  __shared__ float red1[4], red2[4], ys[H];
  float s1 = wredsum(y);
  float s2 = wredsum(y * y);
  int wid = h >> 5;
  if ((h & 31) == 0){ red1[wid] = s1; red2[wid] = s2; }
  __syncthreads();
  float t1 = red1[0] + red1[1] + red1[2] + red1[3];
  float t2 = red2[0] + red2[1] + red2[2] + red2[3];
  float mean = t1 * (1.0f / H);
  float var  = fmaf(-mean, mean, t2 * (1.0f / H));
  float rstd = rsqa(var + EPS);
  ys[h] = fmaf((y - mean) * rstd, lng[h], lnb[h]);
  __syncthreads();
  if (h < A){
    float acc = ab2[h];
    #pragma unroll 8
    for (int k = 0; k < H; ++k) acc = fmaf(ys[k], aw2[k * A + h], acc);
    g_logits[row * A + h] = acc;
  }
}

// ---------------- P3: action log_softmax over dim 1 (sequence) ----------------
__global__ void __launch_bounds__(512) k_actsm(float* __restrict__ out)
{
  int b = blockIdx.x / A, a = blockIdx.x % A;
  int s = threadIdx.x;
  float v = g_logits[(b * S + s) * A + a];

  __shared__ float red[16];
  __shared__ float bmax_s, bsum_s;
  int wid = s >> 5, lane = s & 31;

  float m = wredmax(v);
  if (lane == 0) red[wid] = m;
  __syncthreads();
  if (s < 32){
    float tt = (s < 16) ? red[s] : -3.4e38f;
    tt = wredmax(tt);
    if (s == 0) bmax_s = tt;
  }
  __syncthreads();
  float bmax = bmax_s;
  float e = ex2a((v - bmax) * LOG2E);
  float sm = wredsum(e);
  __syncthreads();
  if (lane == 0) red[wid] = sm;
  __syncthreads();
  if (s < 32){
    float tt = (s < 16) ? red[s] : 0.0f;
    tt = wredsum(tt);
    if (s == 0) bsum_s = tt;
  }
  __syncthreads();
  out[(b * S + s) * A + a] = v - bmax - lg2a(bsum_s) * LN2;
}

// ---------------- P4: pointer heads (f32x2 + HW tanh, prefetch pipeline) -----
// grid (S/4, B, 2), block 256 = 2 j-half groups x 4 warps; warp = one i-row.
// Row-padded smem (65 ulls) -> conflict-free, immediate-offset LDS.
// Register double-buffer: LDG tile t+1 issued before computing tile t.
__global__ void __launch_bounds__(256, 3) k_ptr(
    const float* __restrict__ lg, const float* __restrict__ lb,
    const float* __restrict__ lpw, const float* __restrict__ lpb,
    const float* __restrict__ rg, const float* __restrict__ rb,
    const float* __restrict__ rpw, const float* __restrict__ rpb,
    float* __restrict__ out)
{
  int head = blockIdx.z, b = blockIdx.y;
  int i0 = blockIdx.x * 4;
  const float* gv = head ? rg  : lg;
  const float* bv = head ? rb  : lb;
  const float* pw = head ? rpw : lpw;
  const float* pb = head ? rpb : lpb;
  const float* hv = g_pre[1 + 2 * head] + b * S * H;   // indexed by j
  const float* hd = g_pre[2 + 2 * head] + b * S * H;   // indexed by i

  __shared__ __align__(16) ull  hvs[2][32][65];   // row-padded, conflict-free
  __shared__ __align__(16) float hds[4][H];
  __shared__ __align__(16) float wgh[H];
  __shared__ float redc[4][2];
  __shared__ float cc2[2];
  __shared__ float gmaxs[2][4], gsums[2][4];

  int tid  = threadIdx.x;
  int wid  = tid >> 5, lane = tid & 31;
  int g    = tid >> 7;        // j-half group (0/1)
  int gt   = tid & 127;       // index within group
  int ir   = wid & 3;         // i-row within CTA

  // folded weights: wgh = g*pw ; c1 = sum(g*pw) ; c2 = sum(b*pw) + pb
  if (tid < 128) {
    float p  = pw[tid];
    float wg = gv[tid] * p;
    float tb = bv[tid] * p;
    wgh[tid] = wg;
    float r1 = wredsum(wg), r2 = wredsum(tb);
    if (lane == 0){ redc[wid][0] = r1; redc[wid][1] = r2; }
  }
  for (int idx = tid; idx < 4 * H; idx += 256)
    hds[idx >> 7][idx & (H - 1)] = hd[(i0 + (idx >> 7)) * H + (idx & (H - 1))];
  __syncthreads();
  if (tid == 0){
    cc2[0] = redc[0][0] + redc[1][0] + redc[2][0] + redc[3][0];
    cc2[1] = redc[0][1] + redc[1][1] + redc[2][1] + redc[3][1] + pb[0];
  }
  __syncthreads();
  float c1 = cc2[0], c2 = cc2[1];

  const ull K0p = pk2(TK0, TK0);
  const ull K1p = pk2(TK1, TK1);
  const ull HLp = pk2(0.5f, 0.5f);
  const ull* hv8 = (const ull*)hv;   // 64 ulls per row

  // prefetch registers: this thread's 16 staging slots (rows r0q+{0,2,4,...}, col u0)
  int r0q = gt >> 6;          // 0 or 1: first row of this thread's pair pattern
  int u0  = gt & 63;
  ull pf[16];
  {
    const ull* src = &hv8[(g * 8 * 32) * 64];
    #pragma unroll
    for (int k = 0; k < 16; ++k)
      pf[k] = src[(r0q + k * 2) * 64 + u0];
  }

  float sc[8];
  int barid = 1 + g;

  for (int tile = 0; tile < 8; ++tile) {
    asm volatile("bar.sync %0, 128;" :: "r"(barid) : "memory");
    #pragma unroll
    for (int k = 0; k < 16; ++k)
      hvs[g][r0q + k * 2][u0] = pf[k];
    asm volatile("bar.sync %0, 128;" :: "r"(barid) : "memory");

    if (tile < 7) {
      const ull* src = &hv8[((g * 8 + tile + 1) * 32) * 64];
      #pragma unroll
      for (int k = 0; k < 16; ++k)
        pf[k] = src[(r0q + k * 2) * 64 + u0];
    }

    ull s1 = 0, s2 = 0, s3 = 0;
    const ull* ar = &hvs[g][lane][0];
    const ull* dr = (const ull*)&hds[ir][0];
    const ull* wr = (const ull*)&wgh[0];
    #pragma unroll 8
    for (int q = 0; q < 64; ++q) {
      ull a = ar[q];
      ull d = dr[q];
      ull w = wr[q];
      ull x  = add2(a, d);
      ull x2 = mul2(x, x);
      ull p  = fma2(K1p, x2, K0p);
      ull u  = mul2(x, p);
      float u0f, u1f; upk2(u, u0f, u1f);
      ull t  = pk2(tanha(u0f), tanha(u1f));
      ull xh = mul2(x, HLp);
      ull y  = fma2(xh, t, xh);
      s1 = add2(s1, y);
      s2 = fma2(y, y, s2);
      s3 = fma2(y, w, s3);
    }
    float a0,a1,b0,b1,d0,d1;
    upk2(s1, a0, a1); upk2(s2, b0, b1); upk2(s3, d0, d1);
    float t1 = a0 + a1, t2 = b0 + b1, t3 = d0 + d1;
    float mean = t1 * (1.0f / H);
    float var  = fmaf(-mean, mean, t2 * (1.0f / H));
    float rstd = rsqa(var + EPS);
    sc[tile] = fmaf(rstd, fmaf(-mean, c1, t3), c2);
  }

  // log_softmax over j: combine the two j-half groups per i-row
  float lmax = sc[0];
  #pragma unroll
  for (int k = 1; k < 8; ++k) lmax = fmaxf(lmax, sc[k]);
  lmax = wredmax(lmax);
  if (lane == 0) gmaxs[g][ir] = lmax;
  __syncthreads();
  float m = fmaxf(gmaxs[0][ir], gmaxs[1][ir]);
  float lsum = 0.f;
  #pragma unroll
  for (int k = 0; k < 8; ++k) lsum += ex2a((sc[k] - m) * LOG2E);
  lsum = wredsum(lsum);
  if (lane == 0) gsums[g][ir] = lsum;
  __syncthreads();
  float lse = lg2a(gsums[0][ir] + gsums[1][ir]) * LN2;

  float* orow = out + B * S * A + head * (B * S * S) + (b * S + i0 + ir) * S + g * 256;
  #pragma unroll
  for (int k = 0; k < 8; ++k) orow[k * 32 + lane] = sc[k] - m - lse;
}

extern "C" void kernel_launch(void* const* d_in, const int* in_sizes, int n_in,
                              void* d_out, int out_size)
{
  (void)in_sizes; (void)n_in; (void)out_size;
  const float* hiddens = (const float*)d_in[0];
  const float* aw1     = (const float*)d_in[1];
  const float* ab1     = (const float*)d_in[2];
  const float* a_ln_g  = (const float*)d_in[3];
  const float* a_ln_b  = (const float*)d_in[4];
  const float* aw2     = (const float*)d_in[5];
  const float* ab2     = (const float*)d_in[6];
  const float* lhid_w  = (const float*)d_in[7];
  const float* lhid_b  = (const float*)d_in[8];
  const float* lhead_w = (const float*)d_in[9];
  const float* lhead_b = (const float*)d_in[10];
  const float* l_ln_g  = (const float*)d_in[11];
  const float* l_ln_b  = (const float*)d_in[12];
  const float* l_proj_w= (const float*)d_in[13];
  const float* l_proj_b= (const float*)d_in[14];
  const float* rhid_w  = (const float*)d_in[15];
  const float* rhid_b  = (const float*)d_in[16];
  const float* rhead_w = (const float*)d_in[17];
  const float* rhead_b = (const float*)d_in[18];
  const float* r_ln_g  = (const float*)d_in[19];
  const float* r_ln_b  = (const float*)d_in[20];
  const float* r_proj_w= (const float*)d_in[21];
  const float* r_proj_b= (const float*)d_in[22];
  float* out = (float*)d_out;

  k_gemm<<<dim3(BS / 16, 5), 128>>>(hiddens,
      aw1, ab1, lhid_w, lhid_b, lhead_w, lhead_b, rhid_w, rhid_b, rhead_w, rhead_b);
  k_action<<<BS, 128>>>(a_ln_g, a_ln_b, aw2, ab2);
  k_actsm<<<B * A, 512>>>(out);
  k_ptr<<<dim3(S / 4, B, 2), 256>>>(l_ln_g, l_ln_b, l_proj_w, l_proj_b,
                                    r_ln_g, r_ln_b, r_proj_w, r_proj_b, out);
}